// round 15
// baseline (speedup 1.0000x reference)
#include <cuda_runtime.h>
#include <cuda_fp16.h>
#include <math.h>
#include <cstdint>

// ---------------- scratch (device globals; allocation-free rule) ----------------
__device__ float  g_S [4096*512];      // residual stream fp32 [B,T,D]
__device__ __half g_Sh [4096*512];     // fp16 mirror of S
__device__ __half g_T1h[4096*2048];    // ffn hidden / qkv out fp16
__device__ __half g_T2h[4096*512];     // flash out / gn1 out / dwconv out fp16
__device__ __half g_T3h[4096*512];     // GLU out / gn2 out fp16
__device__ __half g_W  [6029312];      // all transposed fp16 weights
__device__ float  g_BP [1024];         // permuted pw1 bias
__device__ float  g_DD [8*2047];       // rel-pos bias table
__device__ float2 g_part[1024];

// weight offsets (halves)
#define W_FF1A 0u
#define W_FF1B 1048576u
#define W_QKV  2097152u
#define W_OUT  2883584u
#define W_PW1  3145728u
#define W_PW2  3670016u
#define W_FF2A 3932160u
#define W_FF2B 4980736u

__device__ __forceinline__ float gelu_f(float x){
    return 0.5f * x * (1.0f + erff(x * 0.70710678118654752440f));
}
__device__ __forceinline__ float sigm(float x){ return 1.0f/(1.0f + expf(-x)); }

// ---------------- async-copy / ldmatrix helpers ----------------
__device__ __forceinline__ void cpasync16(uint32_t dst, const void* src){
    asm volatile("cp.async.cg.shared.global [%0], [%1], 16;" :: "r"(dst), "l"(src));
}
#define CP_COMMIT() asm volatile("cp.async.commit_group;" ::: "memory")
template<int N>
__device__ __forceinline__ void cp_wait(){
    asm volatile("cp.async.wait_group %0;" :: "n"(N) : "memory");
}
__device__ __forceinline__ void ldsm4(uint32_t* r, uint32_t addr){
    asm volatile("ldmatrix.sync.aligned.m8n8.x4.shared.b16 {%0,%1,%2,%3}, [%4];"
        : "=r"(r[0]), "=r"(r[1]), "=r"(r[2]), "=r"(r[3]) : "r"(addr));
}
__device__ __forceinline__ void ldsm4t(uint32_t* r, uint32_t addr){
    asm volatile("ldmatrix.sync.aligned.m8n8.x4.trans.shared.b16 {%0,%1,%2,%3}, [%4];"
        : "=r"(r[0]), "=r"(r[1]), "=r"(r[2]), "=r"(r[3]) : "r"(addr));
}
// fp16 warp MMA: D(16x8,f32) += A(16x16,f16) * B(16x8,f16)
__device__ __forceinline__ void mma16(float* c, const uint32_t* a, uint32_t b0, uint32_t b1){
    asm volatile(
        "mma.sync.aligned.m16n8k16.row.col.f32.f16.f16.f32 "
        "{%0,%1,%2,%3},{%4,%5,%6,%7},{%8,%9},{%0,%1,%2,%3};"
        : "+f"(c[0]), "+f"(c[1]), "+f"(c[2]), "+f"(c[3])
        : "r"(a[0]), "r"(a[1]), "r"(a[2]), "r"(a[3]), "r"(b0), "r"(b1));
}

// shared epilogue element op
// EPI: 0=bias->f16 | 1=bias+GELU->f16 | 2=bias+res->f32+f16 | 3=bias+GLU->f16
//      4=EPI2+stats | 5=bias+res -> transposed fp32 store into [B,D,T]
template<int EPI>
__device__ __forceinline__ void epi_store(
    int r0, int c, int Cs, float v0, float v1, float v2, float v3,
    const float* __restrict__ res, float* __restrict__ C, __half* __restrict__ Ch,
    float rscale, float& s_sum, float& s_sq)
{
    if (EPI == 1){
        v0=gelu_f(v0); v1=gelu_f(v1); v2=gelu_f(v2); v3=gelu_f(v3);
        *(__half2*)&Ch[(size_t)r0*Cs + c]     = __floats2half2_rn(v0, v1);
        *(__half2*)&Ch[(size_t)(r0+8)*Cs + c] = __floats2half2_rn(v2, v3);
    } else if (EPI == 2 || EPI == 4){
        float2 r0v = *(const float2*)&res[(size_t)r0*Cs + c];
        float2 r1v = *(const float2*)&res[(size_t)(r0+8)*Cs + c];
        v0 = fmaf(rscale, v0, r0v.x); v1 = fmaf(rscale, v1, r0v.y);
        v2 = fmaf(rscale, v2, r1v.x); v3 = fmaf(rscale, v3, r1v.y);
        *(float2*)&C[(size_t)r0*Cs + c]     = make_float2(v0, v1);
        *(float2*)&C[(size_t)(r0+8)*Cs + c] = make_float2(v2, v3);
        *(__half2*)&Ch[(size_t)r0*Cs + c]     = __floats2half2_rn(v0, v1);
        *(__half2*)&Ch[(size_t)(r0+8)*Cs + c] = __floats2half2_rn(v2, v3);
        if (EPI == 4){
            s_sum += v0+v1+v2+v3;
            s_sq  = fmaf(v0,v0,fmaf(v1,v1,fmaf(v2,v2,fmaf(v3,v3,s_sq))));
        }
    } else if (EPI == 3){
        int co = c >> 1;
        Ch[(size_t)r0*Cs + co]     = __float2half(v0 * sigm(v1));
        Ch[(size_t)(r0+8)*Cs + co] = __float2half(v2 * sigm(v3));
    } else if (EPI == 5){
        float2 r0v = *(const float2*)&res[(size_t)r0*Cs + c];
        float2 r1v = *(const float2*)&res[(size_t)(r0+8)*Cs + c];
        v0 = fmaf(rscale, v0, r0v.x); v1 = fmaf(rscale, v1, r0v.y);
        v2 = fmaf(rscale, v2, r1v.x); v3 = fmaf(rscale, v3, r1v.y);
        int bb = r0 >> 10, tt = r0 & 1023;
        float* o0 = C + ((size_t)bb*512 + c)*1024 + tt;
        o0[0] = v0; o0[8] = v2;
        o0[1024] = v1; o0[1024 + 8] = v3;
    } else {
        *(__half2*)&Ch[(size_t)r0*Cs + c]     = __floats2half2_rn(v0, v1);
        *(__half2*)&Ch[(size_t)(r0+8)*Cs + c] = __floats2half2_rn(v2, v3);
    }
}

// ---------------- fp16 tensor GEMM: CTA 128x128, K staged by 64 ----------------
template<int EPI>
__global__ void __launch_bounds__(256,2) hgemm_k(
    const __half* __restrict__ A, const __half* __restrict__ B,
    const float* __restrict__ bias, const float* __restrict__ res,
    float* __restrict__ C, __half* __restrict__ Ch,
    int Kd, float rscale, int Cs, float2* __restrict__ part)
{
    constexpr int NJ   = 4;
    constexpr int ST   = 128*72;

    extern __shared__ __align__(16) __half smh[];
    __half* Ash = smh;                 // [3][128][72]
    __half* Bsh = smh + 3*ST;          // [3][128][72]

    int tid = threadIdx.x, lane = tid & 31, wid = tid >> 5;
    int wr = wid >> 2, wc = wid & 3;
    int g = lane >> 2, tg = lane & 3;
    int row0 = blockIdx.y*128, col0 = blockIdx.x*128;

    const __half* Ag = A + (size_t)row0*Kd;
    const __half* Bg = B + (size_t)col0*Kd;
    uint32_t sA = (uint32_t)__cvta_generic_to_shared(Ash);
    uint32_t sB = (uint32_t)__cvta_generic_to_shared(Bsh);

    auto loadA = [&](int kt, int buf){
        int k0 = kt*64;
        uint32_t base = sA + (uint32_t)(buf*(ST*2));
        #pragma unroll
        for (int i = 0; i < 4; i++){
            int f = tid + i*256;
            int m = f >> 3, seg = f & 7;
            cpasync16(base + (uint32_t)(m*144 + seg*16),
                      Ag + (size_t)m*Kd + k0 + seg*8);
        }
    };
    auto loadB = [&](int kt, int buf){
        int k0 = kt*64;
        uint32_t base = sB + (uint32_t)(buf*(ST*2));
        #pragma unroll
        for (int i = 0; i < 4; i++){
            int f = tid + i*256;
            int n = f >> 3, seg = f & 7;
            cpasync16(base + (uint32_t)(n*144 + seg*16),
                      Bg + (size_t)n*Kd + k0 + seg*8);
        }
    };

    uint32_t aBase = sA + (uint32_t)(((wr*64 + (lane & 15))*72 + ((lane >> 4) << 3)) * 2);
    uint32_t bBase = sB + (uint32_t)(((wc*32 + ((lane >> 4) & 1)*8 + (lane & 7))*72
                                     + (((lane >> 3) & 1) << 3)) * 2);

    float acc[4][NJ][4];
    #pragma unroll
    for (int mi=0;mi<4;mi++)
        #pragma unroll
        for (int nj=0;nj<NJ;nj++)
            #pragma unroll
            for (int q=0;q<4;q++) acc[mi][nj][q]=0.f;

    int nk = Kd >> 6;
    loadA(0,0); loadB(0,0); CP_COMMIT();
    loadA(1,1); loadB(1,1); CP_COMMIT();

    int buf = 0, nbuf = 2;
    for (int kt = 0; kt < nk; ++kt){
        cp_wait<1>();
        __syncthreads();
        if (kt + 2 < nk){ loadA(kt+2, nbuf); loadB(kt+2, nbuf); }
        CP_COMMIT();

        uint32_t aB = aBase + (uint32_t)(buf*ST*2);
        uint32_t bB = bBase + (uint32_t)(buf*ST*2);
        #pragma unroll
        for (int ks = 0; ks < 4; ++ks){
            int k0h = ks*16;
            uint32_t a[4][4];
            #pragma unroll
            for (int mi=0;mi<4;mi++)
                ldsm4(a[mi], aB + (uint32_t)((mi*16*72 + k0h)*2));
            #pragma unroll
            for (int nj2=0;nj2<NJ/2;nj2++){
                uint32_t bb[4];
                ldsm4(bb, bB + (uint32_t)((nj2*16*72 + k0h)*2));
                #pragma unroll
                for (int mi=0;mi<4;mi++)
                    mma16(acc[mi][2*nj2  ], a[mi], bb[0], bb[1]);
                #pragma unroll
                for (int mi=0;mi<4;mi++)
                    mma16(acc[mi][2*nj2+1], a[mi], bb[2], bb[3]);
            }
        }
        buf = (buf == 2) ? 0 : buf+1;
        nbuf = (nbuf == 2) ? 0 : nbuf+1;
    }

    float s_sum = 0.f, s_sq = 0.f;
    #pragma unroll
    for (int nj=0;nj<NJ;nj++){
        int c = col0 + wc*32 + nj*8 + tg*2;
        float2 bi = *(const float2*)&bias[c];
        #pragma unroll
        for (int mi=0;mi<4;mi++){
            int r0 = row0 + wr*64 + mi*16 + g;
            epi_store<EPI>(r0, c, Cs, acc[mi][nj][0]+bi.x, acc[mi][nj][1]+bi.y,
                           acc[mi][nj][2]+bi.x, acc[mi][nj][3]+bi.y,
                           res, C, Ch, rscale, s_sum, s_sq);
        }
    }
    if (EPI == 4){
        __syncthreads();
        float* red = (float*)smh;
        red[tid] = s_sum; red[256 + tid] = s_sq;
        __syncthreads();
        for (int o=128;o>0;o>>=1){
            if (tid < o){ red[tid] += red[tid+o]; red[256+tid] += red[256+tid+o]; }
            __syncthreads();
        }
        if (tid == 0)
            part[blockIdx.y*gridDim.x + blockIdx.x] = make_float2(red[0], red[256]);
    }
}

// ---------------- merged prep: weight transpose+convert, dd table, pw1 bias ----
__global__ void wconv_all(const float* __restrict__ ff1w1, const float* __restrict__ ff1w2,
                          const float* __restrict__ qkvw,  const float* __restrict__ outw,
                          const float* __restrict__ pw1w,  const float* __restrict__ pw2w,
                          const float* __restrict__ ff2w1, const float* __restrict__ ff2w2,
                          __half* __restrict__ W,
                          const float* __restrict__ rel_embed, float* __restrict__ ddt,
                          const float* __restrict__ pw1b, float* __restrict__ bp){
    int bI = blockIdx.x;
    int ltid = threadIdx.y*32 + threadIdx.x;
    if (bI >= 5888){
        if (bI < 5952){
            int idx = (bI - 5888)*256 + ltid;
            if (idx < 8*2047){
                int h = idx / 2047;
                int rpos = idx % 2047;
                int rel = rpos - 1023;
                int sign = (rel >= 0) ? 1 : 0;
                int a = (rel >= 0) ? rel : -rel;
                int bucket;
                if (a < 80) bucket = a;
                else {
                    float lr = logf((float)a / 80.0f) / logf(10.0f);
                    int lp = 80 + (int)(lr * 80.0f);
                    bucket = (lp < 159) ? lp : 159;
                }
                bucket += sign*160;
                if (bucket < 0) bucket = 0;
                if (bucket > 319) bucket = 319;
                ddt[idx] = rel_embed[bucket*8 + h];
            }
        } else {
            #pragma unroll
            for (int i=0;i<4;i++){
                int c = ltid + i*256;
                bp[c] = pw1b[(c>>1) + (c&1)*512];
            }
        }
        return;
    }
    __shared__ float t[32][33];
    const float* src; int K, N, cOff, rStr, tilesX; unsigned base;
    if      (bI < 1024){            src=ff1w1; K=512;  N=2048; cOff=0;   base=W_FF1A;     rStr=1; tilesX=64; }
    else if (bI < 2048){ bI-=1024;  src=ff1w2; K=2048; N=512;  cOff=0;   base=W_FF1B;     rStr=1; tilesX=16; }
    else if (bI < 2816){ bI-=2048;  src=qkvw;  K=512;  N=1536; cOff=0;   base=W_QKV;      rStr=1; tilesX=48; }
    else if (bI < 3072){ bI-=2816;  src=outw;  K=512;  N=512;  cOff=0;   base=W_OUT;      rStr=1; tilesX=16; }
    else if (bI < 3328){ bI-=3072;  src=pw1w;  K=512;  N=1024; cOff=0;   base=W_PW1;      rStr=2; tilesX=16; }
    else if (bI < 3584){ bI-=3328;  src=pw1w;  K=512;  N=1024; cOff=512; base=W_PW1+512u; rStr=2; tilesX=16; }
    else if (bI < 3840){ bI-=3584;  src=pw2w;  K=512;  N=512;  cOff=0;   base=W_PW2;      rStr=1; tilesX=16; }
    else if (bI < 4864){ bI-=3840;  src=ff2w1; K=512;  N=2048; cOff=0;   base=W_FF2A;     rStr=1; tilesX=64; }
    else               { bI-=4864;  src=ff2w2; K=2048; N=512;  cOff=0;   base=W_FF2B;     rStr=1; tilesX=16; }
    int n0 = (bI % tilesX)*32, k0 = (bI / tilesX)*32;
    int lx = threadIdx.x, ly = threadIdx.y;
    #pragma unroll
    for (int i=0;i<32;i+=8)
        t[ly+i][lx] = src[(size_t)(k0+ly+i)*N + cOff + n0 + lx];
    __syncthreads();
    #pragma unroll
    for (int i=0;i<32;i+=8)
        W[base + (size_t)(n0+ly+i)*K*rStr + k0 + lx] = __float2half(t[lx][ly+i]);
}

// ---------------- input transpose ----------------
__global__ void transpose_bdt_btd(const float* __restrict__ in, float* __restrict__ out,
                                  __half* __restrict__ outh){
    __shared__ float tile[32][33];
    int b = blockIdx.z;
    int t0 = blockIdx.x*32, d0 = blockIdx.y*32;
    int lx = threadIdx.x, ly = threadIdx.y;
    #pragma unroll
    for (int i=0;i<32;i+=8)
        tile[ly+i][lx] = in[((size_t)b*512 + d0+ly+i)*1024 + t0 + lx];
    __syncthreads();
    #pragma unroll
    for (int i=0;i<32;i+=8){
        float v = tile[lx][ly+i];
        size_t o = ((size_t)b*1024 + t0+ly+i)*512 + d0 + lx;
        out[o] = v;
        outh[o] = __float2half(v);
    }
}

// ---------------- fp16 flash attention: 128-query blocks, 3-buffer K/V ring ----
__global__ void __launch_bounds__(256) flash_h_k(
    const __half* __restrict__ qkv,    // [B,T,1536] fp16
    const float* __restrict__ gate_u, const float* __restrict__ gate_w,
    const float* __restrict__ gate_scale, const float* __restrict__ ddt,
    __half* __restrict__ outh)         // fp16 [B,T,512]
{
    constexpr int ST = 64*72;
    extern __shared__ __align__(16) __half smh[];
    __half* Qs = smh;                  // [128][72]
    __half* Ks = Qs + 128*72;          // [3][64][72]  row-major [s][d]
    __half* Vs = Ks + 3*ST;            // [3][64][72]  row-major [s][d]
    __half* Ps = Vs + 3*ST;            // [128][72]
    float* dds   = (float*)(Ps + 128*72);  // [3][192]
    float* coefs = dds + 576;              // [128]

    int tid = threadIdx.x, lane = tid & 31, wid = tid >> 5;
    int g = lane >> 2, tg = lane & 3;
    int t0 = blockIdx.x * 128;
    int h  = blockIdx.y;
    int b  = blockIdx.z;
    int m0 = wid * 16;

    const __half* qbase = qkv + (size_t)b*1024*1536 + h*64;
    const __half* kbase = qbase + 512;
    const __half* vbase = qbase + 1024;

    uint32_t sQ = (uint32_t)__cvta_generic_to_shared(Qs);
    uint32_t sK = (uint32_t)__cvta_generic_to_shared(Ks);
    uint32_t sV = (uint32_t)__cvta_generic_to_shared(Vs);
    uint32_t sP = (uint32_t)__cvta_generic_to_shared(Ps);
    uint32_t offA  = (uint32_t)((((lane & 15))*72 + ((lane >> 4) << 3)) * 2);
    uint32_t offB  = (uint32_t)(((((lane >> 4) & 1)*8 + (lane & 7))*72
                                 + (((lane >> 3) & 1) << 3)) * 2);
    uint32_t offBt = (uint32_t)((((lane & 7) + ((lane >> 3) & 1)*8)*72
                                 + (((lane >> 4) & 1) << 3)) * 2);

    auto loadKV = [&](int s0, int kvb){
        uint32_t kb = sK + (uint32_t)(kvb*ST*2);
        uint32_t vb = sV + (uint32_t)(kvb*ST*2);
        const __half* kr = kbase + (size_t)s0*1536;
        const __half* vr = vbase + (size_t)s0*1536;
        #pragma unroll
        for (int i=0;i<2;i++){
            int f = tid + i*256;
            int m = f >> 3, seg = f & 7;
            cpasync16(kb + (uint32_t)(m*144 + seg*16), kr + (size_t)m*1536 + seg*8);
            cpasync16(vb + (uint32_t)(m*144 + seg*16), vr + (size_t)m*1536 + seg*8);
        }
    };

    { // load Q tile (128 rows)
        int m = tid >> 1, hf = (tid & 1) * 32;
        const __half* qr = qbase + (size_t)(t0+m)*1536 + hf;
        #pragma unroll
        for (int i=0;i<4;i++)
            *(uint4*)&Qs[m*72 + hf + i*8] = *(const uint4*)(qr + i*8);
    }
    loadKV(0, 0); CP_COMMIT();
    loadKV(64, 1); CP_COMMIT();
    __syncthreads();
    if (tid < 128){ // per-query gate coefficient
        float du=0.f, dw=0.f;
        #pragma unroll
        for (int d=0; d<64; d++){
            float qv = __half2float(Qs[tid*72 + d]);
            du = fmaf(qv, gate_u[h*64+d], du);
            dw = fmaf(qv, gate_w[h*64+d], dw);
        }
        float gu = sigm(du), gr = sigm(dw);
        coefs[tid] = 1.0f + gu + (1.0f-gu)*gate_scale[h]*gr;
    }
    uint32_t qf[4][4];
    #pragma unroll
    for (int ks=0;ks<4;ks++)
        ldsm4(qf[ks], sQ + (uint32_t)(m0*72*2) + offA + (uint32_t)(ks*16*2));

    float m_run[2] = {-3.0e38f, -3.0e38f}, l_run[2] = {0.f, 0.f};
    float O[8][4];
    #pragma unroll
    for (int nd=0;nd<8;nd++)
        #pragma unroll
        for (int q=0;q<4;q++) O[nd][q]=0.f;

    int kvb = 0;
    for (int it = 0; it < 16; ++it){
        int s0 = it*64;
        if (tid < 191) dds[kvb*192 + tid] = ddt[h*2047 + 896 + (s0 - t0) + tid];
        cp_wait<1>();
        __syncthreads();   // cur K/V + dds visible; prior reads of next write-buf done
        if (it + 2 < 16){
            int nb = kvb + 2; if (nb >= 3) nb -= 3;
            loadKV(s0 + 128, nb);
        }
        CP_COMMIT();
        const float* dd = dds + kvb*192;
        uint32_t kB = sK + (uint32_t)(kvb*ST*2);
        uint32_t vB = sV + (uint32_t)(kvb*ST*2);

        // S = Q K^T  (per warp: 16 rows x 64 keys)
        float S[8][4];
        #pragma unroll
        for (int nj=0;nj<8;nj++)
            #pragma unroll
            for (int q=0;q<4;q++) S[nj][q]=0.f;
        #pragma unroll
        for (int ks=0;ks<4;ks++){
            #pragma unroll
            for (int nj2=0;nj2<4;nj2++){
                uint32_t bb[4];
                ldsm4(bb, kB + offB + (uint32_t)((nj2*16*72 + ks*16)*2));
                mma16(S[2*nj2  ], qf[ks], bb[0], bb[1]);
                mma16(S[2*nj2+1], qf[ks], bb[2], bb[3]);
            }
        }
        // bias: S*0.125 + coef[row]*dd[col-row+127]
        float c0 = coefs[m0+g], c1 = coefs[m0+g+8];
        #pragma unroll
        for (int nj=0;nj<8;nj++){
            int cn = nj*8 + tg*2;
            float dd0 = dd[cn     - (m0+g)   + 127];
            float dd1 = dd[cn + 1 - (m0+g)   + 127];
            float dd2 = dd[cn     - (m0+g+8) + 127];
            float dd3 = dd[cn + 1 - (m0+g+8) + 127];
            S[nj][0] = fmaf(S[nj][0], 0.125f, c0*dd0);
            S[nj][1] = fmaf(S[nj][1], 0.125f, c0*dd1);
            S[nj][2] = fmaf(S[nj][2], 0.125f, c1*dd2);
            S[nj][3] = fmaf(S[nj][3], 0.125f, c1*dd3);
        }
        // online softmax (per warp rows)
        #pragma unroll
        for (int i=0;i<2;i++){
            float mx = -3.0e38f;
            #pragma unroll
            for (int nj=0;nj<8;nj++) mx = fmaxf(mx, fmaxf(S[nj][2*i], S[nj][2*i+1]));
            mx = fmaxf(mx, __shfl_xor_sync(0xffffffffu, mx, 1));
            mx = fmaxf(mx, __shfl_xor_sync(0xffffffffu, mx, 2));
            float mo = fmaxf(m_run[i], mx);
            float alpha = __expf(m_run[i] - mo);
            m_run[i] = mo;
            float ls = 0.f;
            #pragma unroll
            for (int nj=0;nj<8;nj++){
                float p0 = __expf(S[nj][2*i]   - mo);
                float p1 = __expf(S[nj][2*i+1] - mo);
                S[nj][2*i] = p0; S[nj][2*i+1] = p1;
                ls += p0 + p1;
            }
            ls += __shfl_xor_sync(0xffffffffu, ls, 1);
            ls += __shfl_xor_sync(0xffffffffu, ls, 2);
            l_run[i] = l_run[i]*alpha + ls;
            #pragma unroll
            for (int nd=0;nd<8;nd++){ O[nd][2*i] *= alpha; O[nd][2*i+1] *= alpha; }
        }
        // write P fp16 (per-warp region)
        #pragma unroll
        for (int nj=0;nj<8;nj++){
            *(__half2*)&Ps[(m0+g  )*72 + nj*8 + tg*2] = __floats2half2_rn(S[nj][0], S[nj][1]);
            *(__half2*)&Ps[(m0+g+8)*72 + nj*8 + tg*2] = __floats2half2_rn(S[nj][2], S[nj][3]);
        }
        __syncwarp();
        // O += P V
        #pragma unroll
        for (int ko=0;ko<4;ko++){
            uint32_t pa[4];
            ldsm4(pa, sP + (uint32_t)(m0*72*2) + offA + (uint32_t)(ko*16*2));
            #pragma unroll
            for (int nd2=0;nd2<4;nd2++){
                uint32_t bb[4];
                ldsm4t(bb, vB + offBt + (uint32_t)((ko*16*72 + nd2*16)*2));
                mma16(O[2*nd2  ], pa, bb[0], bb[1]);
                mma16(O[2*nd2+1], pa, bb[2], bb[3]);
            }
        }
        kvb = (kvb == 2) ? 0 : kvb + 1;
    }
    float inv0 = 1.0f / l_run[0], inv1 = 1.0f / l_run[1];
    int r0 = t0 + m0 + g;
    #pragma unroll
    for (int nd=0;nd<8;nd++){
        int c = h*64 + nd*8 + tg*2;
        *(__half2*)&outh[((size_t)(b*1024 + r0  ))*512 + c] = __floats2half2_rn(O[nd][0]*inv0, O[nd][1]*inv0);
        *(__half2*)&outh[((size_t)(b*1024 + r0+8))*512 + c] = __floats2half2_rn(O[nd][2]*inv1, O[nd][3]*inv1);
    }
}

// ---------------- GroupNorm apply with inline parallel finalize ----------------
template<bool SILU_, bool HIN_>
__global__ void gn_apply_k(const void* __restrict__ xin, const float2* __restrict__ part,
                           int np, const float* __restrict__ g, const float* __restrict__ be,
                           __half* __restrict__ y){
    __shared__ float ssum[64], ssq[64];
    size_t i4 = (size_t)blockIdx.x*256 + threadIdx.x;
    int b = (int)(i4 >> 17);
    if (threadIdx.x < 64){
        if (threadIdx.x < np){
            float2 v = part[b*np + threadIdx.x];
            ssum[threadIdx.x] = v.x; ssq[threadIdx.x] = v.y;
        } else { ssum[threadIdx.x] = 0.f; ssq[threadIdx.x] = 0.f; }
    }
    __syncthreads();
    if (threadIdx.x < 32){
        ssum[threadIdx.x] += ssum[threadIdx.x+32];
        ssq[threadIdx.x]  += ssq[threadIdx.x+32];
        #pragma unroll
        for (int o=16;o>0;o>>=1){
            ssum[threadIdx.x] += __shfl_down_sync(0xffffffffu, ssum[threadIdx.x], o);
            ssq[threadIdx.x]  += __shfl_down_sync(0xffffffffu, ssq[threadIdx.x], o);
        }
        if (threadIdx.x == 0){
            float mean = ssum[0]*(1.0f/524288.0f);
            float var  = ssq[0]*(1.0f/524288.0f) - mean*mean;
            ssum[0] = mean; ssq[0] = rsqrtf(var + 1e-5f);
        }
    }
    __syncthreads();
    float mean = ssum[0], inv = ssq[0];
    int d = (int)((i4 & 127) << 2);
    float4 xv;
    if (HIN_){
        const __half2* xp = (const __half2*)((const __half*)xin + i4*4);
        float2 lo = __half22float2(xp[0]);
        float2 hi = __half22float2(xp[1]);
        xv = make_float4(lo.x, lo.y, hi.x, hi.y);
    } else {
        xv = *(const float4*)((const float*)xin + i4*4);
    }
    float4 gv = *(const float4*)(g + d);
    float4 bv = *(const float4*)(be + d);
    float4 o;
    o.x = (xv.x-mean)*inv*gv.x + bv.x;
    o.y = (xv.y-mean)*inv*gv.y + bv.y;
    o.z = (xv.z-mean)*inv*gv.z + bv.z;
    o.w = (xv.w-mean)*inv*gv.w + bv.w;
    if (SILU_){
        o.x *= sigm(o.x); o.y *= sigm(o.y); o.z *= sigm(o.z); o.w *= sigm(o.w);
    }
    __half2* yp = (__half2*)(y + i4*4);
    yp[0] = __floats2half2_rn(o.x, o.y);
    yp[1] = __floats2half2_rn(o.z, o.w);
}

// ---------------- depthwise conv (fp16 in/out, smem-tiled) + fused GN2 stats ---
__global__ void __launch_bounds__(512) dwconv_k(
    const __half* __restrict__ in, const float* __restrict__ w,
    const float* __restrict__ bias, __half* __restrict__ out,
    float2* __restrict__ part)
{
    __shared__ __half tile[46][512];
    int d = threadIdx.x;
    int tt0 = blockIdx.x * 16;
    int b = blockIdx.y;
    const __half* base = in + (size_t)b*524288;
    #pragma unroll
    for (int i=0;i<46;i++){
        int t = tt0 - 15 + i;
        tile[i][d] = (t >= 0 && t < 1024) ? base[(size_t)t*512 + d] : __float2half(0.f);
    }
    float wr[31];
    #pragma unroll
    for (int k=0;k<31;k++) wr[k] = w[d*31+k];
    float bi = bias[d];
    __syncthreads();
    float s_sum = 0.f, s_sq = 0.f;
    #pragma unroll
    for (int j=0;j<16;j++){
        float acc = bi;
        #pragma unroll
        for (int k=0;k<31;k++) acc = fmaf(__half2float(tile[j+k][d]), wr[k], acc);
        out[((size_t)b*1024 + tt0 + j)*512 + d] = __float2half(acc);
        s_sum += acc;
        s_sq = fmaf(acc, acc, s_sq);
    }
    __syncthreads();
    float* red = (float*)&tile[0][0];
    red[d] = s_sum; red[512 + d] = s_sq;
    __syncthreads();
    for (int o=256;o>0;o>>=1){
        if (d < o){ red[d] += red[d+o]; red[512+d] += red[512+d+o]; }
        __syncthreads();
    }
    if (d == 0) part[b*64 + blockIdx.x] = make_float2(red[0], red[512]);
}

// ---------------- launch ----------------
extern "C" void kernel_launch(void* const* d_in, const int* in_sizes, int n_in,
                              void* d_out, int out_size) {
    const float* x      = (const float*)d_in[0];
    const float* ff1_w1 = (const float*)d_in[1];
    const float* ff1_b1 = (const float*)d_in[2];
    const float* ff1_w2 = (const float*)d_in[3];
    const float* ff1_b2 = (const float*)d_in[4];
    const float* qkv_w  = (const float*)d_in[5];
    const float* qkv_b  = (const float*)d_in[6];
    const float* out_w  = (const float*)d_in[7];
    const float* out_b  = (const float*)d_in[8];
    const float* gn1_g  = (const float*)d_in[9];
    const float* gn1_b  = (const float*)d_in[10];
    const float* pw1_w  = (const float*)d_in[11];
    const float* pw1_b  = (const float*)d_in[12];
    const float* dw_w   = (const float*)d_in[13];
    const float* dw_b   = (const float*)d_in[14];
    const float* gn2_g  = (const float*)d_in[15];
    const float* gn2_b  = (const float*)d_in[16];
    const float* pw2_w  = (const float*)d_in[17];
    const float* pw2_b  = (const float*)d_in[18];
    const float* ff2_w1 = (const float*)d_in[19];
    const float* ff2_b1 = (const float*)d_in[20];
    const float* ff2_w2 = (const float*)d_in[21];
    const float* ff2_b2 = (const float*)d_in[22];
    const float* rel_e  = (const float*)d_in[23];
    const float* gate_u = (const float*)d_in[24];
    const float* gate_w = (const float*)d_in[25];
    const float* gate_s = (const float*)d_in[26];

    float *S, *DDp, *BP;
    __half *Sh, *T1h, *T2h, *T3h, *W;
    float2 *PART;
    cudaGetSymbolAddress((void**)&S,  g_S);
    cudaGetSymbolAddress((void**)&Sh, g_Sh);
    cudaGetSymbolAddress((void**)&T1h,g_T1h);
    cudaGetSymbolAddress((void**)&T2h,g_T2h);
    cudaGetSymbolAddress((void**)&T3h,g_T3h);
    cudaGetSymbolAddress((void**)&W,  g_W);
    cudaGetSymbolAddress((void**)&BP, g_BP);
    cudaGetSymbolAddress((void**)&DDp,g_DD);
    cudaGetSymbolAddress((void**)&PART, g_part);

    const int FLASH_SMEM = (128*72 + 6*64*72 + 128*72)*2 + 576*4 + 128*4;  // 94976
    cudaFuncSetAttribute((const void*)flash_h_k,
                         cudaFuncAttributeMaxDynamicSharedMemorySize, FLASH_SMEM);
    const int GS = 3*2*(128*72)*2;   // 110592
    cudaFuncSetAttribute(hgemm_k<0>, cudaFuncAttributeMaxDynamicSharedMemorySize, GS);
    cudaFuncSetAttribute(hgemm_k<1>, cudaFuncAttributeMaxDynamicSharedMemorySize, GS);
    cudaFuncSetAttribute(hgemm_k<2>, cudaFuncAttributeMaxDynamicSharedMemorySize, GS);
    cudaFuncSetAttribute(hgemm_k<3>, cudaFuncAttributeMaxDynamicSharedMemorySize, GS);
    cudaFuncSetAttribute(hgemm_k<4>, cudaFuncAttributeMaxDynamicSharedMemorySize, GS);
    cudaFuncSetAttribute(hgemm_k<5>, cudaFuncAttributeMaxDynamicSharedMemorySize, GS);

    dim3 tb(32,8);
    // prep (one merged kernel + input transpose)
    transpose_bdt_btd<<<dim3(32,16,4), tb>>>(x, S, Sh);
    wconv_all<<<5953, tb>>>(ff1_w1, ff1_w2, qkv_w, out_w, pw1_w, pw2_w, ff2_w1, ff2_w2,
                            W, rel_e, DDp, pw1_b, BP);

    // FFN1 (half-step)
    hgemm_k<1><<<dim3(16,32),256,GS>>>(Sh,  W+W_FF1A, ff1_b1, nullptr, nullptr, T1h, 512, 0.f, 2048, nullptr);
    hgemm_k<2><<<dim3( 4,32),256,GS>>>(T1h, W+W_FF1B, ff1_b2, S, S, Sh, 2048, 0.5f, 512, nullptr);
    // QKV (fp16 out)
    hgemm_k<0><<<dim3(12,32),256,GS>>>(Sh,  W+W_QKV,  qkv_b,  nullptr, nullptr, T1h, 512, 0.f, 1536, nullptr);
    // attention (128-query blocks)
    flash_h_k<<<dim3(8,8,4),256,FLASH_SMEM>>>(T1h, gate_u, gate_w, gate_s, DDp, T2h);
    // out-proj + residual + fused GN1 stats (32 partials per batch)
    hgemm_k<4><<<dim3( 4,32),256,GS>>>(T2h, W+W_OUT,  out_b,  S, S, Sh, 512, 1.0f, 512, PART);
    gn_apply_k<false,false><<<2048,256>>>(S, PART, 32, gn1_g, gn1_b, T2h);
    // pw1 + fused GLU (fp16 out)
    hgemm_k<3><<<dim3( 8,32),256,GS>>>(T2h, W+W_PW1, BP, nullptr, nullptr, T3h, 512, 0.f, 512, nullptr);
    // dwconv (fp16 in/out) + fused GN2 stats (64 partials per batch)
    dwconv_k<<<dim3(64,4),512>>>(T3h, dw_w, dw_b, T2h, PART);
    gn_apply_k<true,true><<<2048,256>>>(T2h, PART, 64, gn2_g, gn2_b, T3h);
    hgemm_k<2><<<dim3( 4,32),256,GS>>>(T3h, W+W_PW2,  pw2_b,  S, S, Sh, 512, 1.0f, 512, nullptr);
    // FFN2 (half-step); final GEMM stores directly transposed into d_out
    hgemm_k<1><<<dim3(16,32),256,GS>>>(Sh,  W+W_FF2A, ff2_b1, nullptr, nullptr, T1h, 512, 0.f, 2048, nullptr);
    hgemm_k<5><<<dim3( 4,32),256,GS>>>(T1h, W+W_FF2B, ff2_b2, S, (float*)d_out, nullptr, 2048, 0.5f, 512, nullptr);
}

// round 16
// speedup vs baseline: 1.0215x; 1.0215x over previous
#include <cuda_runtime.h>
#include <cuda_fp16.h>
#include <math.h>
#include <cstdint>

// ---------------- scratch (device globals; allocation-free rule) ----------------
__device__ float  g_S [4096*512];      // residual stream fp32 [B,T,D]
__device__ __half g_Sh [4096*512];     // fp16 mirror of S
__device__ __half g_T1h[4096*2048];    // ffn hidden / qkv out fp16
__device__ __half g_T2h[4096*512];     // flash out / gn1 out / dwconv out fp16
__device__ __half g_T3h[4096*512];     // GLU out / gn2 out fp16
__device__ __half g_W  [6029312];      // all transposed fp16 weights
__device__ float  g_BP [1024];         // permuted pw1 bias
__device__ float  g_DD [8*2047];       // rel-pos bias table
__device__ float2 g_part[1024];

// weight offsets (halves)
#define W_FF1A 0u
#define W_FF1B 1048576u
#define W_QKV  2097152u
#define W_OUT  2883584u
#define W_PW1  3145728u
#define W_PW2  3670016u
#define W_FF2A 3932160u
#define W_FF2B 4980736u

__device__ __forceinline__ float gelu_f(float x){
    return 0.5f * x * (1.0f + erff(x * 0.70710678118654752440f));
}
__device__ __forceinline__ float sigm(float x){ return 1.0f/(1.0f + expf(-x)); }

// ---------------- async-copy / ldmatrix helpers ----------------
__device__ __forceinline__ void cpasync16(uint32_t dst, const void* src){
    asm volatile("cp.async.cg.shared.global [%0], [%1], 16;" :: "r"(dst), "l"(src));
}
#define CP_COMMIT() asm volatile("cp.async.commit_group;" ::: "memory")
template<int N>
__device__ __forceinline__ void cp_wait(){
    asm volatile("cp.async.wait_group %0;" :: "n"(N) : "memory");
}
__device__ __forceinline__ void ldsm4(uint32_t* r, uint32_t addr){
    asm volatile("ldmatrix.sync.aligned.m8n8.x4.shared.b16 {%0,%1,%2,%3}, [%4];"
        : "=r"(r[0]), "=r"(r[1]), "=r"(r[2]), "=r"(r[3]) : "r"(addr));
}
__device__ __forceinline__ void ldsm4t(uint32_t* r, uint32_t addr){
    asm volatile("ldmatrix.sync.aligned.m8n8.x4.trans.shared.b16 {%0,%1,%2,%3}, [%4];"
        : "=r"(r[0]), "=r"(r[1]), "=r"(r[2]), "=r"(r[3]) : "r"(addr));
}
// fp16 warp MMA: D(16x8,f32) += A(16x16,f16) * B(16x8,f16)
__device__ __forceinline__ void mma16(float* c, const uint32_t* a, uint32_t b0, uint32_t b1){
    asm volatile(
        "mma.sync.aligned.m16n8k16.row.col.f32.f16.f16.f32 "
        "{%0,%1,%2,%3},{%4,%5,%6,%7},{%8,%9},{%0,%1,%2,%3};"
        : "+f"(c[0]), "+f"(c[1]), "+f"(c[2]), "+f"(c[3])
        : "r"(a[0]), "r"(a[1]), "r"(a[2]), "r"(a[3]), "r"(b0), "r"(b1));
}

// shared epilogue element op
// EPI: 0=bias->f16 | 1=bias+GELU->f16 | 2=bias+res->f32+f16 | 3=bias+GLU->f16
//      4=EPI2+stats | 5=bias+res -> transposed fp32 store into [B,D,T]
template<int EPI>
__device__ __forceinline__ void epi_store(
    int r0, int c, int Cs, float v0, float v1, float v2, float v3,
    const float* __restrict__ res, float* __restrict__ C, __half* __restrict__ Ch,
    float rscale, float& s_sum, float& s_sq)
{
    if (EPI == 1){
        v0=gelu_f(v0); v1=gelu_f(v1); v2=gelu_f(v2); v3=gelu_f(v3);
        *(__half2*)&Ch[(size_t)r0*Cs + c]     = __floats2half2_rn(v0, v1);
        *(__half2*)&Ch[(size_t)(r0+8)*Cs + c] = __floats2half2_rn(v2, v3);
    } else if (EPI == 2 || EPI == 4){
        float2 r0v = *(const float2*)&res[(size_t)r0*Cs + c];
        float2 r1v = *(const float2*)&res[(size_t)(r0+8)*Cs + c];
        v0 = fmaf(rscale, v0, r0v.x); v1 = fmaf(rscale, v1, r0v.y);
        v2 = fmaf(rscale, v2, r1v.x); v3 = fmaf(rscale, v3, r1v.y);
        *(float2*)&C[(size_t)r0*Cs + c]     = make_float2(v0, v1);
        *(float2*)&C[(size_t)(r0+8)*Cs + c] = make_float2(v2, v3);
        *(__half2*)&Ch[(size_t)r0*Cs + c]     = __floats2half2_rn(v0, v1);
        *(__half2*)&Ch[(size_t)(r0+8)*Cs + c] = __floats2half2_rn(v2, v3);
        if (EPI == 4){
            s_sum += v0+v1+v2+v3;
            s_sq  = fmaf(v0,v0,fmaf(v1,v1,fmaf(v2,v2,fmaf(v3,v3,s_sq))));
        }
    } else if (EPI == 3){
        int co = c >> 1;
        Ch[(size_t)r0*Cs + co]     = __float2half(v0 * sigm(v1));
        Ch[(size_t)(r0+8)*Cs + co] = __float2half(v2 * sigm(v3));
    } else if (EPI == 5){
        float2 r0v = *(const float2*)&res[(size_t)r0*Cs + c];
        float2 r1v = *(const float2*)&res[(size_t)(r0+8)*Cs + c];
        v0 = fmaf(rscale, v0, r0v.x); v1 = fmaf(rscale, v1, r0v.y);
        v2 = fmaf(rscale, v2, r1v.x); v3 = fmaf(rscale, v3, r1v.y);
        int bb = r0 >> 10, tt = r0 & 1023;
        float* o0 = C + ((size_t)bb*512 + c)*1024 + tt;
        o0[0] = v0; o0[8] = v2;
        o0[1024] = v1; o0[1024 + 8] = v3;
    } else {
        *(__half2*)&Ch[(size_t)r0*Cs + c]     = __floats2half2_rn(v0, v1);
        *(__half2*)&Ch[(size_t)(r0+8)*Cs + c] = __floats2half2_rn(v2, v3);
    }
}

// ---------------- fp16 tensor GEMM: CTA 128x128, K staged by 64 ----------------
template<int EPI>
__global__ void __launch_bounds__(256,2) hgemm_k(
    const __half* __restrict__ A, const __half* __restrict__ B,
    const float* __restrict__ bias, const float* __restrict__ res,
    float* __restrict__ C, __half* __restrict__ Ch,
    int Kd, float rscale, int Cs, float2* __restrict__ part)
{
    constexpr int NJ   = 4;
    constexpr int ST   = 128*72;

    extern __shared__ __align__(16) __half smh[];
    __half* Ash = smh;                 // [3][128][72]
    __half* Bsh = smh + 3*ST;          // [3][128][72]

    int tid = threadIdx.x, lane = tid & 31, wid = tid >> 5;
    int wr = wid >> 2, wc = wid & 3;
    int g = lane >> 2, tg = lane & 3;
    int row0 = blockIdx.y*128, col0 = blockIdx.x*128;

    const __half* Ag = A + (size_t)row0*Kd;
    const __half* Bg = B + (size_t)col0*Kd;
    uint32_t sA = (uint32_t)__cvta_generic_to_shared(Ash);
    uint32_t sB = (uint32_t)__cvta_generic_to_shared(Bsh);

    auto loadA = [&](int kt, int buf){
        int k0 = kt*64;
        uint32_t base = sA + (uint32_t)(buf*(ST*2));
        #pragma unroll
        for (int i = 0; i < 4; i++){
            int f = tid + i*256;
            int m = f >> 3, seg = f & 7;
            cpasync16(base + (uint32_t)(m*144 + seg*16),
                      Ag + (size_t)m*Kd + k0 + seg*8);
        }
    };
    auto loadB = [&](int kt, int buf){
        int k0 = kt*64;
        uint32_t base = sB + (uint32_t)(buf*(ST*2));
        #pragma unroll
        for (int i = 0; i < 4; i++){
            int f = tid + i*256;
            int n = f >> 3, seg = f & 7;
            cpasync16(base + (uint32_t)(n*144 + seg*16),
                      Bg + (size_t)n*Kd + k0 + seg*8);
        }
    };

    uint32_t aBase = sA + (uint32_t)(((wr*64 + (lane & 15))*72 + ((lane >> 4) << 3)) * 2);
    uint32_t bBase = sB + (uint32_t)(((wc*32 + ((lane >> 4) & 1)*8 + (lane & 7))*72
                                     + (((lane >> 3) & 1) << 3)) * 2);

    float acc[4][NJ][4];
    #pragma unroll
    for (int mi=0;mi<4;mi++)
        #pragma unroll
        for (int nj=0;nj<NJ;nj++)
            #pragma unroll
            for (int q=0;q<4;q++) acc[mi][nj][q]=0.f;

    int nk = Kd >> 6;
    loadA(0,0); loadB(0,0); CP_COMMIT();
    loadA(1,1); loadB(1,1); CP_COMMIT();

    int buf = 0, nbuf = 2;
    for (int kt = 0; kt < nk; ++kt){
        cp_wait<1>();
        __syncthreads();
        if (kt + 2 < nk){ loadA(kt+2, nbuf); loadB(kt+2, nbuf); }
        CP_COMMIT();

        uint32_t aB = aBase + (uint32_t)(buf*ST*2);
        uint32_t bB = bBase + (uint32_t)(buf*ST*2);
        #pragma unroll
        for (int ks = 0; ks < 4; ++ks){
            int k0h = ks*16;
            uint32_t a[4][4];
            #pragma unroll
            for (int mi=0;mi<4;mi++)
                ldsm4(a[mi], aB + (uint32_t)((mi*16*72 + k0h)*2));
            #pragma unroll
            for (int nj2=0;nj2<NJ/2;nj2++){
                uint32_t bb[4];
                ldsm4(bb, bB + (uint32_t)((nj2*16*72 + k0h)*2));
                #pragma unroll
                for (int mi=0;mi<4;mi++)
                    mma16(acc[mi][2*nj2  ], a[mi], bb[0], bb[1]);
                #pragma unroll
                for (int mi=0;mi<4;mi++)
                    mma16(acc[mi][2*nj2+1], a[mi], bb[2], bb[3]);
            }
        }
        buf = (buf == 2) ? 0 : buf+1;
        nbuf = (nbuf == 2) ? 0 : nbuf+1;
    }

    float s_sum = 0.f, s_sq = 0.f;
    #pragma unroll
    for (int nj=0;nj<NJ;nj++){
        int c = col0 + wc*32 + nj*8 + tg*2;
        float2 bi = *(const float2*)&bias[c];
        #pragma unroll
        for (int mi=0;mi<4;mi++){
            int r0 = row0 + wr*64 + mi*16 + g;
            epi_store<EPI>(r0, c, Cs, acc[mi][nj][0]+bi.x, acc[mi][nj][1]+bi.y,
                           acc[mi][nj][2]+bi.x, acc[mi][nj][3]+bi.y,
                           res, C, Ch, rscale, s_sum, s_sq);
        }
    }
    if (EPI == 4){
        __syncthreads();
        float* red = (float*)smh;
        red[tid] = s_sum; red[256 + tid] = s_sq;
        __syncthreads();
        for (int o=128;o>0;o>>=1){
            if (tid < o){ red[tid] += red[tid+o]; red[256+tid] += red[256+tid+o]; }
            __syncthreads();
        }
        if (tid == 0)
            part[blockIdx.y*gridDim.x + blockIdx.x] = make_float2(red[0], red[256]);
    }
}

// ---------------- merged prep: weight transpose+convert, dd table, pw1 bias ----
__global__ void wconv_all(const float* __restrict__ ff1w1, const float* __restrict__ ff1w2,
                          const float* __restrict__ qkvw,  const float* __restrict__ outw,
                          const float* __restrict__ pw1w,  const float* __restrict__ pw2w,
                          const float* __restrict__ ff2w1, const float* __restrict__ ff2w2,
                          __half* __restrict__ W,
                          const float* __restrict__ rel_embed, float* __restrict__ ddt,
                          const float* __restrict__ pw1b, float* __restrict__ bp){
    int bI = blockIdx.x;
    int ltid = threadIdx.y*32 + threadIdx.x;
    if (bI >= 5888){
        if (bI < 5952){
            int idx = (bI - 5888)*256 + ltid;
            if (idx < 8*2047){
                int h = idx / 2047;
                int rpos = idx % 2047;
                int rel = rpos - 1023;
                int sign = (rel >= 0) ? 1 : 0;
                int a = (rel >= 0) ? rel : -rel;
                int bucket;
                if (a < 80) bucket = a;
                else {
                    float lr = logf((float)a / 80.0f) / logf(10.0f);
                    int lp = 80 + (int)(lr * 80.0f);
                    bucket = (lp < 159) ? lp : 159;
                }
                bucket += sign*160;
                if (bucket < 0) bucket = 0;
                if (bucket > 319) bucket = 319;
                ddt[idx] = rel_embed[bucket*8 + h];
            }
        } else {
            #pragma unroll
            for (int i=0;i<4;i++){
                int c = ltid + i*256;
                bp[c] = pw1b[(c>>1) + (c&1)*512];
            }
        }
        return;
    }
    __shared__ float t[32][33];
    const float* src; int K, N, cOff, rStr, tilesX; unsigned base;
    if      (bI < 1024){            src=ff1w1; K=512;  N=2048; cOff=0;   base=W_FF1A;     rStr=1; tilesX=64; }
    else if (bI < 2048){ bI-=1024;  src=ff1w2; K=2048; N=512;  cOff=0;   base=W_FF1B;     rStr=1; tilesX=16; }
    else if (bI < 2816){ bI-=2048;  src=qkvw;  K=512;  N=1536; cOff=0;   base=W_QKV;      rStr=1; tilesX=48; }
    else if (bI < 3072){ bI-=2816;  src=outw;  K=512;  N=512;  cOff=0;   base=W_OUT;      rStr=1; tilesX=16; }
    else if (bI < 3328){ bI-=3072;  src=pw1w;  K=512;  N=1024; cOff=0;   base=W_PW1;      rStr=2; tilesX=16; }
    else if (bI < 3584){ bI-=3328;  src=pw1w;  K=512;  N=1024; cOff=512; base=W_PW1+512u; rStr=2; tilesX=16; }
    else if (bI < 3840){ bI-=3584;  src=pw2w;  K=512;  N=512;  cOff=0;   base=W_PW2;      rStr=1; tilesX=16; }
    else if (bI < 4864){ bI-=3840;  src=ff2w1; K=512;  N=2048; cOff=0;   base=W_FF2A;     rStr=1; tilesX=64; }
    else               { bI-=4864;  src=ff2w2; K=2048; N=512;  cOff=0;   base=W_FF2B;     rStr=1; tilesX=16; }
    int n0 = (bI % tilesX)*32, k0 = (bI / tilesX)*32;
    int lx = threadIdx.x, ly = threadIdx.y;
    #pragma unroll
    for (int i=0;i<32;i+=8)
        t[ly+i][lx] = src[(size_t)(k0+ly+i)*N + cOff + n0 + lx];
    __syncthreads();
    #pragma unroll
    for (int i=0;i<32;i+=8)
        W[base + (size_t)(n0+ly+i)*K*rStr + k0 + lx] = __float2half(t[lx][ly+i]);
}

// ---------------- input transpose ----------------
__global__ void transpose_bdt_btd(const float* __restrict__ in, float* __restrict__ out,
                                  __half* __restrict__ outh){
    __shared__ float tile[32][33];
    int b = blockIdx.z;
    int t0 = blockIdx.x*32, d0 = blockIdx.y*32;
    int lx = threadIdx.x, ly = threadIdx.y;
    #pragma unroll
    for (int i=0;i<32;i+=8)
        tile[ly+i][lx] = in[((size_t)b*512 + d0+ly+i)*1024 + t0 + lx];
    __syncthreads();
    #pragma unroll
    for (int i=0;i<32;i+=8){
        float v = tile[lx][ly+i];
        size_t o = ((size_t)b*1024 + t0+ly+i)*512 + d0 + lx;
        out[o] = v;
        outh[o] = __float2half(v);
    }
}

// ---------------- fp16 flash attention: 64-query blocks, 3-buffer K/V ring -----
__global__ void __launch_bounds__(128) flash_h_k(
    const __half* __restrict__ qkv,    // [B,T,1536] fp16
    const float* __restrict__ gate_u, const float* __restrict__ gate_w,
    const float* __restrict__ gate_scale, const float* __restrict__ ddt,
    __half* __restrict__ outh)         // fp16 [B,T,512]
{
    constexpr int ST = 64*72;
    extern __shared__ __align__(16) __half smh[];
    __half* Qs = smh;                  // [64][72]
    __half* Ks = Qs + ST;              // [3][64][72]  row-major [s][d]
    __half* Vs = Ks + 3*ST;            // [3][64][72]  row-major [s][d]
    __half* Ps = Vs + 3*ST;            // [64][72]
    float* dds   = (float*)(Ps + ST);  // [3][128]
    float* coefs = dds + 384;          // [64]

    int tid = threadIdx.x, lane = tid & 31, wid = tid >> 5;
    int g = lane >> 2, tg = lane & 3;
    int t0 = blockIdx.x * 64;
    int h  = blockIdx.y;
    int b  = blockIdx.z;
    int m0 = wid * 16;

    const __half* qbase = qkv + (size_t)b*1024*1536 + h*64;
    const __half* kbase = qbase + 512;
    const __half* vbase = qbase + 1024;

    uint32_t sQ = (uint32_t)__cvta_generic_to_shared(Qs);
    uint32_t sK = (uint32_t)__cvta_generic_to_shared(Ks);
    uint32_t sV = (uint32_t)__cvta_generic_to_shared(Vs);
    uint32_t sP = (uint32_t)__cvta_generic_to_shared(Ps);
    uint32_t offA  = (uint32_t)((((lane & 15))*72 + ((lane >> 4) << 3)) * 2);
    uint32_t offB  = (uint32_t)(((((lane >> 4) & 1)*8 + (lane & 7))*72
                                 + (((lane >> 3) & 1) << 3)) * 2);
    uint32_t offBt = (uint32_t)((((lane & 7) + ((lane >> 3) & 1)*8)*72
                                 + (((lane >> 4) & 1) << 3)) * 2);

    auto loadKV = [&](int s0, int kvb){
        uint32_t kb = sK + (uint32_t)(kvb*ST*2);
        uint32_t vb = sV + (uint32_t)(kvb*ST*2);
        const __half* kr = kbase + (size_t)s0*1536;
        const __half* vr = vbase + (size_t)s0*1536;
        #pragma unroll
        for (int i=0;i<4;i++){
            int f = tid + i*128;
            int m = f >> 3, seg = f & 7;
            cpasync16(kb + (uint32_t)(m*144 + seg*16), kr + (size_t)m*1536 + seg*8);
            cpasync16(vb + (uint32_t)(m*144 + seg*16), vr + (size_t)m*1536 + seg*8);
        }
    };

    { // load Q tile
        int m = tid >> 1, hf = (tid & 1) * 32;
        const __half* qr = qbase + (size_t)(t0+m)*1536 + hf;
        #pragma unroll
        for (int i=0;i<4;i++)
            *(uint4*)&Qs[m*72 + hf + i*8] = *(const uint4*)(qr + i*8);
    }
    loadKV(0, 0); CP_COMMIT();
    loadKV(64, 1); CP_COMMIT();
    __syncthreads();
    if (tid < 64){ // per-query gate coefficient
        float du=0.f, dw=0.f;
        #pragma unroll
        for (int d=0; d<64; d++){
            float qv = __half2float(Qs[tid*72 + d]);
            du = fmaf(qv, gate_u[h*64+d], du);
            dw = fmaf(qv, gate_w[h*64+d], dw);
        }
        float gu = sigm(du), gr = sigm(dw);
        coefs[tid] = 1.0f + gu + (1.0f-gu)*gate_scale[h]*gr;
    }
    uint32_t qf[4][4];
    #pragma unroll
    for (int ks=0;ks<4;ks++)
        ldsm4(qf[ks], sQ + (uint32_t)(m0*72*2) + offA + (uint32_t)(ks*16*2));

    float m_run[2] = {-3.0e38f, -3.0e38f}, l_run[2] = {0.f, 0.f};
    float O[8][4];
    #pragma unroll
    for (int nd=0;nd<8;nd++)
        #pragma unroll
        for (int q=0;q<4;q++) O[nd][q]=0.f;

    int kvb = 0;
    for (int it = 0; it < 16; ++it){
        int s0 = it*64;
        if (tid < 127) dds[kvb*128 + tid] = ddt[h*2047 + 960 + (s0 - t0) + tid];
        cp_wait<1>();
        __syncthreads();   // cur K/V + dds visible; prior reads of next write-buf done
        if (it + 2 < 16){
            int nb = kvb + 2; if (nb >= 3) nb -= 3;
            loadKV(s0 + 128, nb);
        }
        CP_COMMIT();
        const float* dd = dds + kvb*128;
        uint32_t kB = sK + (uint32_t)(kvb*ST*2);
        uint32_t vB = sV + (uint32_t)(kvb*ST*2);

        // S = Q K^T
        float S[8][4];
        #pragma unroll
        for (int nj=0;nj<8;nj++)
            #pragma unroll
            for (int q=0;q<4;q++) S[nj][q]=0.f;
        #pragma unroll
        for (int ks=0;ks<4;ks++){
            #pragma unroll
            for (int nj2=0;nj2<4;nj2++){
                uint32_t bb[4];
                ldsm4(bb, kB + offB + (uint32_t)((nj2*16*72 + ks*16)*2));
                mma16(S[2*nj2  ], qf[ks], bb[0], bb[1]);
                mma16(S[2*nj2+1], qf[ks], bb[2], bb[3]);
            }
        }
        // bias: S*0.125 + coef[row]*dd[col-row+63]
        float c0 = coefs[m0+g], c1 = coefs[m0+g+8];
        #pragma unroll
        for (int nj=0;nj<8;nj++){
            int cn = nj*8 + tg*2;
            float dd0 = dd[cn     - (m0+g)   + 63];
            float dd1 = dd[cn + 1 - (m0+g)   + 63];
            float dd2 = dd[cn     - (m0+g+8) + 63];
            float dd3 = dd[cn + 1 - (m0+g+8) + 63];
            S[nj][0] = fmaf(S[nj][0], 0.125f, c0*dd0);
            S[nj][1] = fmaf(S[nj][1], 0.125f, c0*dd1);
            S[nj][2] = fmaf(S[nj][2], 0.125f, c1*dd2);
            S[nj][3] = fmaf(S[nj][3], 0.125f, c1*dd3);
        }
        // online softmax
        #pragma unroll
        for (int i=0;i<2;i++){
            float mx = -3.0e38f;
            #pragma unroll
            for (int nj=0;nj<8;nj++) mx = fmaxf(mx, fmaxf(S[nj][2*i], S[nj][2*i+1]));
            mx = fmaxf(mx, __shfl_xor_sync(0xffffffffu, mx, 1));
            mx = fmaxf(mx, __shfl_xor_sync(0xffffffffu, mx, 2));
            float mo = fmaxf(m_run[i], mx);
            float alpha = __expf(m_run[i] - mo);
            m_run[i] = mo;
            float ls = 0.f;
            #pragma unroll
            for (int nj=0;nj<8;nj++){
                float p0 = __expf(S[nj][2*i]   - mo);
                float p1 = __expf(S[nj][2*i+1] - mo);
                S[nj][2*i] = p0; S[nj][2*i+1] = p1;
                ls += p0 + p1;
            }
            ls += __shfl_xor_sync(0xffffffffu, ls, 1);
            ls += __shfl_xor_sync(0xffffffffu, ls, 2);
            l_run[i] = l_run[i]*alpha + ls;
            #pragma unroll
            for (int nd=0;nd<8;nd++){ O[nd][2*i] *= alpha; O[nd][2*i+1] *= alpha; }
        }
        // write P fp16 (per-warp region)
        #pragma unroll
        for (int nj=0;nj<8;nj++){
            *(__half2*)&Ps[(m0+g  )*72 + nj*8 + tg*2] = __floats2half2_rn(S[nj][0], S[nj][1]);
            *(__half2*)&Ps[(m0+g+8)*72 + nj*8 + tg*2] = __floats2half2_rn(S[nj][2], S[nj][3]);
        }
        __syncwarp();
        // O += P V
        #pragma unroll
        for (int ko=0;ko<4;ko++){
            uint32_t pa[4];
            ldsm4(pa, sP + (uint32_t)(m0*72*2) + offA + (uint32_t)(ko*16*2));
            #pragma unroll
            for (int nd2=0;nd2<4;nd2++){
                uint32_t bb[4];
                ldsm4t(bb, vB + offBt + (uint32_t)((ko*16*72 + nd2*16)*2));
                mma16(O[2*nd2  ], pa, bb[0], bb[1]);
                mma16(O[2*nd2+1], pa, bb[2], bb[3]);
            }
        }
        kvb = (kvb == 2) ? 0 : kvb + 1;
    }
    float inv0 = 1.0f / l_run[0], inv1 = 1.0f / l_run[1];
    int r0 = t0 + m0 + g;
    #pragma unroll
    for (int nd=0;nd<8;nd++){
        int c = h*64 + nd*8 + tg*2;
        *(__half2*)&outh[((size_t)(b*1024 + r0  ))*512 + c] = __floats2half2_rn(O[nd][0]*inv0, O[nd][1]*inv0);
        *(__half2*)&outh[((size_t)(b*1024 + r0+8))*512 + c] = __floats2half2_rn(O[nd][2]*inv1, O[nd][3]*inv1);
    }
}

// ---------------- GroupNorm apply with inline parallel finalize ----------------
template<bool SILU_, bool HIN_>
__global__ void gn_apply_k(const void* __restrict__ xin, const float2* __restrict__ part,
                           int np, const float* __restrict__ g, const float* __restrict__ be,
                           __half* __restrict__ y){
    __shared__ float ssum[64], ssq[64];
    size_t i4 = (size_t)blockIdx.x*256 + threadIdx.x;
    int b = (int)(i4 >> 17);
    if (threadIdx.x < 64){
        if (threadIdx.x < np){
            float2 v = part[b*np + threadIdx.x];
            ssum[threadIdx.x] = v.x; ssq[threadIdx.x] = v.y;
        } else { ssum[threadIdx.x] = 0.f; ssq[threadIdx.x] = 0.f; }
    }
    __syncthreads();
    if (threadIdx.x < 32){
        ssum[threadIdx.x] += ssum[threadIdx.x+32];
        ssq[threadIdx.x]  += ssq[threadIdx.x+32];
        #pragma unroll
        for (int o=16;o>0;o>>=1){
            ssum[threadIdx.x] += __shfl_down_sync(0xffffffffu, ssum[threadIdx.x], o);
            ssq[threadIdx.x]  += __shfl_down_sync(0xffffffffu, ssq[threadIdx.x], o);
        }
        if (threadIdx.x == 0){
            float mean = ssum[0]*(1.0f/524288.0f);
            float var  = ssq[0]*(1.0f/524288.0f) - mean*mean;
            ssum[0] = mean; ssq[0] = rsqrtf(var + 1e-5f);
        }
    }
    __syncthreads();
    float mean = ssum[0], inv = ssq[0];
    int d = (int)((i4 & 127) << 2);
    float4 xv;
    if (HIN_){
        const __half2* xp = (const __half2*)((const __half*)xin + i4*4);
        float2 lo = __half22float2(xp[0]);
        float2 hi = __half22float2(xp[1]);
        xv = make_float4(lo.x, lo.y, hi.x, hi.y);
    } else {
        xv = *(const float4*)((const float*)xin + i4*4);
    }
    float4 gv = *(const float4*)(g + d);
    float4 bv = *(const float4*)(be + d);
    float4 o;
    o.x = (xv.x-mean)*inv*gv.x + bv.x;
    o.y = (xv.y-mean)*inv*gv.y + bv.y;
    o.z = (xv.z-mean)*inv*gv.z + bv.z;
    o.w = (xv.w-mean)*inv*gv.w + bv.w;
    if (SILU_){
        o.x *= sigm(o.x); o.y *= sigm(o.y); o.z *= sigm(o.z); o.w *= sigm(o.w);
    }
    __half2* yp = (__half2*)(y + i4*4);
    yp[0] = __floats2half2_rn(o.x, o.y);
    yp[1] = __floats2half2_rn(o.z, o.w);
}

// ---------------- depthwise conv (fp16 in/out, smem-tiled) + fused GN2 stats ---
__global__ void __launch_bounds__(512) dwconv_k(
    const __half* __restrict__ in, const float* __restrict__ w,
    const float* __restrict__ bias, __half* __restrict__ out,
    float2* __restrict__ part)
{
    __shared__ __half tile[46][512];
    int d = threadIdx.x;
    int tt0 = blockIdx.x * 16;
    int b = blockIdx.y;
    const __half* base = in + (size_t)b*524288;
    #pragma unroll
    for (int i=0;i<46;i++){
        int t = tt0 - 15 + i;
        tile[i][d] = (t >= 0 && t < 1024) ? base[(size_t)t*512 + d] : __float2half(0.f);
    }
    float wr[31];
    #pragma unroll
    for (int k=0;k<31;k++) wr[k] = w[d*31+k];
    float bi = bias[d];
    __syncthreads();
    float s_sum = 0.f, s_sq = 0.f;
    #pragma unroll
    for (int j=0;j<16;j++){
        float acc = bi;
        #pragma unroll
        for (int k=0;k<31;k++) acc = fmaf(__half2float(tile[j+k][d]), wr[k], acc);
        out[((size_t)b*1024 + tt0 + j)*512 + d] = __float2half(acc);
        s_sum += acc;
        s_sq = fmaf(acc, acc, s_sq);
    }
    __syncthreads();
    float* red = (float*)&tile[0][0];
    red[d] = s_sum; red[512 + d] = s_sq;
    __syncthreads();
    for (int o=256;o>0;o>>=1){
        if (d < o){ red[d] += red[d+o]; red[512+d] += red[512+d+o]; }
        __syncthreads();
    }
    if (d == 0) part[b*64 + blockIdx.x] = make_float2(red[0], red[512]);
}

// ---------------- launch ----------------
extern "C" void kernel_launch(void* const* d_in, const int* in_sizes, int n_in,
                              void* d_out, int out_size) {
    const float* x      = (const float*)d_in[0];
    const float* ff1_w1 = (const float*)d_in[1];
    const float* ff1_b1 = (const float*)d_in[2];
    const float* ff1_w2 = (const float*)d_in[3];
    const float* ff1_b2 = (const float*)d_in[4];
    const float* qkv_w  = (const float*)d_in[5];
    const float* qkv_b  = (const float*)d_in[6];
    const float* out_w  = (const float*)d_in[7];
    const float* out_b  = (const float*)d_in[8];
    const float* gn1_g  = (const float*)d_in[9];
    const float* gn1_b  = (const float*)d_in[10];
    const float* pw1_w  = (const float*)d_in[11];
    const float* pw1_b  = (const float*)d_in[12];
    const float* dw_w   = (const float*)d_in[13];
    const float* dw_b   = (const float*)d_in[14];
    const float* gn2_g  = (const float*)d_in[15];
    const float* gn2_b  = (const float*)d_in[16];
    const float* pw2_w  = (const float*)d_in[17];
    const float* pw2_b  = (const float*)d_in[18];
    const float* ff2_w1 = (const float*)d_in[19];
    const float* ff2_b1 = (const float*)d_in[20];
    const float* ff2_w2 = (const float*)d_in[21];
    const float* ff2_b2 = (const float*)d_in[22];
    const float* rel_e  = (const float*)d_in[23];
    const float* gate_u = (const float*)d_in[24];
    const float* gate_w = (const float*)d_in[25];
    const float* gate_s = (const float*)d_in[26];

    float *S, *DDp, *BP;
    __half *Sh, *T1h, *T2h, *T3h, *W;
    float2 *PART;
    cudaGetSymbolAddress((void**)&S,  g_S);
    cudaGetSymbolAddress((void**)&Sh, g_Sh);
    cudaGetSymbolAddress((void**)&T1h,g_T1h);
    cudaGetSymbolAddress((void**)&T2h,g_T2h);
    cudaGetSymbolAddress((void**)&T3h,g_T3h);
    cudaGetSymbolAddress((void**)&W,  g_W);
    cudaGetSymbolAddress((void**)&BP, g_BP);
    cudaGetSymbolAddress((void**)&DDp,g_DD);
    cudaGetSymbolAddress((void**)&PART, g_part);

    const int FLASH_SMEM = 8*64*72*2 + 384*4 + 64*4;   // 75520
    cudaFuncSetAttribute((const void*)flash_h_k,
                         cudaFuncAttributeMaxDynamicSharedMemorySize, FLASH_SMEM);
    const int GS = 3*2*(128*72)*2;   // 110592
    cudaFuncSetAttribute(hgemm_k<0>, cudaFuncAttributeMaxDynamicSharedMemorySize, GS);
    cudaFuncSetAttribute(hgemm_k<1>, cudaFuncAttributeMaxDynamicSharedMemorySize, GS);
    cudaFuncSetAttribute(hgemm_k<2>, cudaFuncAttributeMaxDynamicSharedMemorySize, GS);
    cudaFuncSetAttribute(hgemm_k<3>, cudaFuncAttributeMaxDynamicSharedMemorySize, GS);
    cudaFuncSetAttribute(hgemm_k<4>, cudaFuncAttributeMaxDynamicSharedMemorySize, GS);
    cudaFuncSetAttribute(hgemm_k<5>, cudaFuncAttributeMaxDynamicSharedMemorySize, GS);

    dim3 tb(32,8);
    // prep (one merged kernel + input transpose)
    transpose_bdt_btd<<<dim3(32,16,4), tb>>>(x, S, Sh);
    wconv_all<<<5953, tb>>>(ff1_w1, ff1_w2, qkv_w, out_w, pw1_w, pw2_w, ff2_w1, ff2_w2,
                            W, rel_e, DDp, pw1_b, BP);

    // FFN1 (half-step)
    hgemm_k<1><<<dim3(16,32),256,GS>>>(Sh,  W+W_FF1A, ff1_b1, nullptr, nullptr, T1h, 512, 0.f, 2048, nullptr);
    hgemm_k<2><<<dim3( 4,32),256,GS>>>(T1h, W+W_FF1B, ff1_b2, S, S, Sh, 2048, 0.5f, 512, nullptr);
    // QKV (fp16 out)
    hgemm_k<0><<<dim3(12,32),256,GS>>>(Sh,  W+W_QKV,  qkv_b,  nullptr, nullptr, T1h, 512, 0.f, 1536, nullptr);
    // attention (64-query blocks, 512 CTAs)
    flash_h_k<<<dim3(16,8,4),128,FLASH_SMEM>>>(T1h, gate_u, gate_w, gate_s, DDp, T2h);
    // out-proj + residual + fused GN1 stats (32 partials per batch)
    hgemm_k<4><<<dim3( 4,32),256,GS>>>(T2h, W+W_OUT,  out_b,  S, S, Sh, 512, 1.0f, 512, PART);
    gn_apply_k<false,false><<<2048,256>>>(S, PART, 32, gn1_g, gn1_b, T2h);
    // pw1 + fused GLU (fp16 out)
    hgemm_k<3><<<dim3( 8,32),256,GS>>>(T2h, W+W_PW1, BP, nullptr, nullptr, T3h, 512, 0.f, 512, nullptr);
    // dwconv (fp16 in/out) + fused GN2 stats (64 partials per batch)
    dwconv_k<<<dim3(64,4),512>>>(T3h, dw_w, dw_b, T2h, PART);
    gn_apply_k<true,true><<<2048,256>>>(T2h, PART, 64, gn2_g, gn2_b, T3h);
    hgemm_k<2><<<dim3( 4,32),256,GS>>>(T3h, W+W_PW2,  pw2_b,  S, S, Sh, 512, 1.0f, 512, nullptr);
    // FFN2 (half-step); final GEMM stores directly transposed into d_out
    hgemm_k<1><<<dim3(16,32),256,GS>>>(Sh,  W+W_FF2A, ff2_b1, nullptr, nullptr, T1h, 512, 0.f, 2048, nullptr);
    hgemm_k<5><<<dim3( 4,32),256,GS>>>(T1h, W+W_FF2B, ff2_b2, S, (float*)d_out, nullptr, 2048, 0.5f, 512, nullptr);
}